// round 12
// baseline (speedup 1.0000x reference)
#include <cuda_runtime.h>
#include <math.h>

#define NB 32
#define NA 5
#define NCH 160          // NA * (19 + 13)
#define NHW 76
#define HW (NHW * NHW)   // 5776
#define HW4 (HW / 4)     // 1444
#define NT 50
#define TSTRIDE 21
#define IMW 640.0f
#define IMH 480.0f
#define TH 80.0f
#define SHARP 2.0f

#define GRID 148
#define TPB 256

__device__ double g_acc = 0.0;
__device__ unsigned int g_done = 0;

__device__ __forceinline__ float sigmoidf_(float x) {
    return 1.0f / (1.0f + expf(-x));
}

// fast sigmoid for the bulk background sum (MUFU-based exp)
__device__ __forceinline__ float sigmoidf_fast(float x) {
    return 1.0f / (1.0f + __expf(-x));
}

__global__ void __launch_bounds__(TPB, 1)
k_fused(const float* __restrict__ O, const float* __restrict__ T,
        float* __restrict__ out) {
    float acc = 0.0f;
    const int t = threadIdx.x;

    // ---------------- per-target section (blocks 0..NB-1) ----------------
    if (blockIdx.x < NB) {
        const int b = blockIdx.x;
        __shared__ int s_gi[NT], s_gj[NT], s_nz[NT], s_valid[NT];

        if (t < NT) {
            float c0 = T[b * (NT * TSTRIDE) + t * TSTRIDE + 1];
            float c1 = T[b * (NT * TSTRIDE) + t * TSTRIDE + 2];
            s_gi[t] = (int)floorf(c0 * (float)NHW);
            s_gj[t] = (int)floorf(c1 * (float)NHW);
            s_nz[t] = (c0 != 0.0f) ? 1 : 0;
        }
        __syncthreads();
        if (t == 0) {
            int v = 1;
            for (int i = 0; i < NT; i++) { v &= s_nz[i]; s_valid[i] = v; }
        }
        __syncthreads();

        bool active = (t < NT) && s_valid[t];
        int gi = 0, gj = 0;
        if (active) {
            gi = s_gi[t]; gj = s_gj[t];
            // OOB scatter indices are dropped by XLA
            if (gi < 0 || gi >= NHW || gj < 0 || gj >= NHW) active = false;
        }
        if (active) {
            // last-write-wins: skip if a later valid target hits the same cell
            for (int t2 = t + 1; t2 < NT && s_valid[t2]; t2++) {
                if (s_gi[t2] == gi && s_gj[t2] == gj) { active = false; break; }
            }
        }
        if (active) {
            float coords[18];
            const float* tp = T + b * (NT * TSTRIDE) + t * TSTRIDE + 1;
#pragma unroll
            for (int c = 0; c < 18; c++) coords[c] = tp[c];

            const float* base = O + (size_t)b * NCH * HW + (size_t)gj * NHW + gi;
            float raw[19];
#pragma unroll
            for (int c = 0; c < 19; c++) raw[c] = base[(size_t)c * HW];

            float lxy = 0.0f;
#pragma unroll
            for (int c = 0; c < 18; c++) {
                float pred = (c < 2) ? sigmoidf_(raw[c]) : raw[c];
                float g = (c & 1) ? (float)gj : (float)gi;
                float tv = coords[c] * (float)NHW - g;
                float d = pred - tv;
                lxy += d * d;
            }

            float csum = 0.0f;
#pragma unroll
            for (int k = 0; k < 9; k++) {
                float xp = (k == 0) ? sigmoidf_(raw[0]) : raw[2 * k];
                float yp = (k == 0) ? sigmoidf_(raw[1]) : raw[2 * k + 1];
                float px = (xp + (float)gi) / (float)NHW;
                float py = (yp + (float)gj) / (float)NHW;
                float dx = (coords[2 * k]     - px) * IMW;
                float dy = (coords[2 * k + 1] - py) * IMH;
                float dn = sqrtf(dx * dx + dy * dy);
                float cv = (dn < TH) ? (expf(SHARP * (1.0f - dn / TH)) - 1.0f) : 0.0f;
                csum += cv;
            }
            float conf_t = (csum / 9.0f) / (expf(SHARP) - 1.0f + 1e-05f);

            float conf = sigmoidf_(raw[18]);
            float dc = conf - conf_t;
            // obj term replaces the generic conf^2 counted in the background loop
            acc += 0.5f * (5.0f * dc * dc - conf * conf) + 0.5f * lxy;
        }
    }

    // ---------------- background conf term, float4-vectorized ----------------
    {
        const unsigned NP = NB * NA;          // 160 conf planes
        const unsigned N4 = NP * HW4;         // total float4s
        for (unsigned idx = blockIdx.x * TPB + t; idx < N4; idx += GRID * TPB) {
            unsigned p4 = idx % HW4;
            unsigned r = idx / HW4;
            unsigned a = r % NA;
            unsigned b = r / NA;
            const float4* pl = (const float4*)(O + (size_t)b * NCH * HW +
                                               (size_t)(a * 32 + 18) * HW);
            float4 v = pl[p4];
            float s0 = sigmoidf_fast(v.x), s1 = sigmoidf_fast(v.y);
            float s2 = sigmoidf_fast(v.z), s3 = sigmoidf_fast(v.w);
            acc += 0.5f * (s0 * s0 + s1 * s1 + s2 * s2 + s3 * s3);
        }
    }

    // ---------------- block reduction -> one double atomic ----------------
    for (int off = 16; off > 0; off >>= 1)
        acc += __shfl_down_sync(0xFFFFFFFFu, acc, off);
    __shared__ float warp_sums[TPB / 32];
    int lane = t & 31, wid = t >> 5;
    if (lane == 0) warp_sums[wid] = acc;
    __syncthreads();
    if (wid == 0) {
        float s = (lane < (TPB / 32)) ? warp_sums[lane] : 0.0f;
        for (int off = 4; off > 0; off >>= 1)
            s += __shfl_down_sync(0xFFFFFFFFu, s, off);
        if (lane == 0) atomicAdd(&g_acc, (double)s);
    }

    // ---------------- last block writes output and resets state ----------------
    __threadfence();
    __syncthreads();
    if (t == 0) {
        unsigned int ticket = atomicAdd(&g_done, 1u);
        if (ticket == GRID - 1) {
            out[0] = (float)g_acc;
            g_acc = 0.0;       // reset for next (graph-replayed) launch
            g_done = 0;
        }
    }
}

extern "C" void kernel_launch(void* const* d_in, const int* in_sizes, int n_in,
                              void* d_out, int out_size) {
    const float* O = (const float*)d_in[0];
    const float* T = (const float*)d_in[1];
    float* out = (float*)d_out;
    (void)in_sizes; (void)n_in; (void)out_size;

    k_fused<<<GRID, TPB>>>(O, T, out);
}

// round 13
// speedup vs baseline: 1.0331x; 1.0331x over previous
#include <cuda_runtime.h>
#include <math.h>

#define NB 32
#define NA 5
#define NCH 160          // NA * (19 + 13)
#define NHW 76
#define HW (NHW * NHW)   // 5776
#define HW4 (HW / 4)     // 1444
#define NT 50
#define TSTRIDE 21
#define IMW 640.0f
#define IMH 480.0f
#define TH 80.0f
#define SHARP 2.0f

#define TPB 256
#define N4_TOTAL (NB * NA * HW4)                 // 231040 float4s
#define GRID ((N4_TOTAL + TPB - 1) / TPB)        // 903 blocks -> 1 float4/thread

__device__ double g_acc = 0.0;
__device__ unsigned int g_done = 0;

__device__ __forceinline__ float sigmoidf_(float x) {
    return 1.0f / (1.0f + expf(-x));
}

// fast sigmoid for the bulk background sum (MUFU-based exp)
__device__ __forceinline__ float sigmoidf_fast(float x) {
    return 1.0f / (1.0f + __expf(-x));
}

__global__ void __launch_bounds__(TPB)
k_fused(const float* __restrict__ O, const float* __restrict__ T,
        float* __restrict__ out) {
    float acc = 0.0f;
    const int t = threadIdx.x;

    // ------- background conf term: exactly ONE float4 per thread -------
    // Issue the load FIRST so it overlaps the target-section work below.
    {
        unsigned idx = blockIdx.x * TPB + t;
        if (idx < N4_TOTAL) {
            unsigned p4 = idx % HW4;
            unsigned r = idx / HW4;
            unsigned a = r % NA;
            unsigned b = r / NA;
            const float4* pl = (const float4*)(O + (size_t)b * NCH * HW +
                                               (size_t)(a * 32 + 18) * HW);
            float4 v = pl[p4];
            float s0 = sigmoidf_fast(v.x), s1 = sigmoidf_fast(v.y);
            float s2 = sigmoidf_fast(v.z), s3 = sigmoidf_fast(v.w);
            acc = 0.5f * (s0 * s0 + s1 * s1 + s2 * s2 + s3 * s3);
        }
    }

    // ---------------- per-target section (blocks 0..NB-1) ----------------
    if (blockIdx.x < NB) {
        const int b = blockIdx.x;
        __shared__ int s_gi[NT], s_gj[NT], s_nz[NT], s_valid[NT];

        if (t < NT) {
            float c0 = T[b * (NT * TSTRIDE) + t * TSTRIDE + 1];
            float c1 = T[b * (NT * TSTRIDE) + t * TSTRIDE + 2];
            s_gi[t] = (int)floorf(c0 * (float)NHW);
            s_gj[t] = (int)floorf(c1 * (float)NHW);
            s_nz[t] = (c0 != 0.0f) ? 1 : 0;
        }
        __syncthreads();
        if (t == 0) {
            int v = 1;
            for (int i = 0; i < NT; i++) { v &= s_nz[i]; s_valid[i] = v; }
        }
        __syncthreads();

        bool active = (t < NT) && s_valid[t];
        int gi = 0, gj = 0;
        if (active) {
            gi = s_gi[t]; gj = s_gj[t];
            // OOB scatter indices are dropped by XLA
            if (gi < 0 || gi >= NHW || gj < 0 || gj >= NHW) active = false;
        }
        if (active) {
            // last-write-wins: skip if a later valid target hits the same cell
            for (int t2 = t + 1; t2 < NT && s_valid[t2]; t2++) {
                if (s_gi[t2] == gi && s_gj[t2] == gj) { active = false; break; }
            }
        }
        if (active) {
            float coords[18];
            const float* tp = T + b * (NT * TSTRIDE) + t * TSTRIDE + 1;
#pragma unroll
            for (int c = 0; c < 18; c++) coords[c] = tp[c];

            const float* base = O + (size_t)b * NCH * HW + (size_t)gj * NHW + gi;
            float raw[19];
#pragma unroll
            for (int c = 0; c < 19; c++) raw[c] = base[(size_t)c * HW];

            float lxy = 0.0f;
#pragma unroll
            for (int c = 0; c < 18; c++) {
                float pred = (c < 2) ? sigmoidf_(raw[c]) : raw[c];
                float g = (c & 1) ? (float)gj : (float)gi;
                float tv = coords[c] * (float)NHW - g;
                float d = pred - tv;
                lxy += d * d;
            }

            float csum = 0.0f;
#pragma unroll
            for (int k = 0; k < 9; k++) {
                float xp = (k == 0) ? sigmoidf_(raw[0]) : raw[2 * k];
                float yp = (k == 0) ? sigmoidf_(raw[1]) : raw[2 * k + 1];
                float px = (xp + (float)gi) / (float)NHW;
                float py = (yp + (float)gj) / (float)NHW;
                float dx = (coords[2 * k]     - px) * IMW;
                float dy = (coords[2 * k + 1] - py) * IMH;
                float dn = sqrtf(dx * dx + dy * dy);
                float cv = (dn < TH) ? (expf(SHARP * (1.0f - dn / TH)) - 1.0f) : 0.0f;
                csum += cv;
            }
            float conf_t = (csum / 9.0f) / (expf(SHARP) - 1.0f + 1e-05f);

            float conf = sigmoidf_(raw[18]);
            float dc = conf - conf_t;
            // obj term replaces the generic conf^2 counted in the background loop
            acc += 0.5f * (5.0f * dc * dc - conf * conf) + 0.5f * lxy;
        }
    }

    // ---------------- block reduction -> one double atomic ----------------
    for (int off = 16; off > 0; off >>= 1)
        acc += __shfl_down_sync(0xFFFFFFFFu, acc, off);
    __shared__ float warp_sums[TPB / 32];
    int lane = t & 31, wid = t >> 5;
    if (lane == 0) warp_sums[wid] = acc;
    __syncthreads();
    if (wid == 0) {
        float s = (lane < (TPB / 32)) ? warp_sums[lane] : 0.0f;
        for (int off = 4; off > 0; off >>= 1)
            s += __shfl_down_sync(0xFFFFFFFFu, s, off);
        if (lane == 0) atomicAdd(&g_acc, (double)s);
    }

    // ---------------- last block writes output and resets state ----------------
    __threadfence();
    __syncthreads();
    if (t == 0) {
        unsigned int ticket = atomicAdd(&g_done, 1u);
        if (ticket == GRID - 1) {
            out[0] = (float)g_acc;
            g_acc = 0.0;       // reset for next (graph-replayed) launch
            g_done = 0;
        }
    }
}

extern "C" void kernel_launch(void* const* d_in, const int* in_sizes, int n_in,
                              void* d_out, int out_size) {
    const float* O = (const float*)d_in[0];
    const float* T = (const float*)d_in[1];
    float* out = (float*)d_out;
    (void)in_sizes; (void)n_in; (void)out_size;

    k_fused<<<GRID, TPB>>>(O, T, out);
}